// round 1
// baseline (speedup 1.0000x reference)
#include <cuda_runtime.h>

#define NN 50000
#define NEMAX 1000000

// ---------------- scratch (no allocations allowed) ----------------
// g_zero: everything that must be zeroed each call
//   [out_deg(NN) | in_deg(NN) | agg1(64*NN) | agg2(32*NN) | agg3(16*NN)]
// g_work: non-zeroed intermediates
//   [norm_src(NN) | norm_dst(NN) | y1(64*NN) | h1(64*NN) | p2(32*NN) | p3(16*NN)]
__device__ __align__(256) float g_zero[(2 + 64 + 32 + 16) * NN];
__device__ __align__(256) float g_work[(2 + 64 + 64 + 32 + 16) * NN];

#define OFF_ODEG 0
#define OFF_IDEG (NN)
#define OFF_AGG1 (2 * NN)
#define OFF_AGG2 (66 * NN)
#define OFF_AGG3 (98 * NN)
#define ZERO_FLOATS (114 * NN)

#define OFF_NSRC 0
#define OFF_NDST (NN)
#define OFF_Y1 (2 * NN)
#define OFF_H1 (66 * NN)
#define OFF_P2 (130 * NN)
#define OFF_P3 (162 * NN)

__device__ __forceinline__ void red_add_v4(float* addr, float4 v) {
    asm volatile("red.global.add.v4.f32 [%0], {%1, %2, %3, %4};"
                 :: "l"(addr), "f"(v.x), "f"(v.y), "f"(v.z), "f"(v.w)
                 : "memory");
}

// ---------------- kernels ----------------

__global__ void k_zero() {
    int i = blockIdx.x * blockDim.x + threadIdx.x;
    if (i < ZERO_FLOATS / 4) {
        ((float4*)g_zero)[i] = make_float4(0.f, 0.f, 0.f, 0.f);
    }
}

__global__ void k_deg(const int* __restrict__ src, const int* __restrict__ dst, int E) {
    int e = blockIdx.x * blockDim.x + threadIdx.x;
    if (e < E) {
        atomicAdd(&g_zero[OFF_ODEG + src[e]], 1.0f);
        atomicAdd(&g_zero[OFF_IDEG + dst[e]], 1.0f);
    }
}

__global__ void k_norm() {
    int i = blockIdx.x * blockDim.x + threadIdx.x;
    if (i < NN) {
        g_work[OFF_NSRC + i] = rsqrtf(fmaxf(g_zero[OFF_ODEG + i], 1.0f));
        g_work[OFF_NDST + i] = rsqrtf(fmaxf(g_zero[OFF_IDEG + i], 1.0f));
    }
}

// y1 = in_feat * norm_src  (per-node row scaling), 64 floats/row = 16 float4
__global__ void k_scale_x(const float* __restrict__ x) {
    int t = blockIdx.x * blockDim.x + threadIdx.x;
    if (t >= NN * 16) return;
    int n = t >> 4;
    float s = g_work[OFF_NSRC + n];
    float4 v = __ldg((const float4*)x + t);
    v.x *= s; v.y *= s; v.z *= s; v.w *= s;
    ((float4*)(g_work + OFF_Y1))[t] = v;
}

// scatter: agg[dst] += msg[src], row = C float4 chunks (C in {16,8,4})
template <int C, int LOGC, int MOFF, int AOFF>
__global__ void k_scatter(const int* __restrict__ src, const int* __restrict__ dst, int E) {
    int t = blockIdx.x * blockDim.x + threadIdx.x;
    int e = t >> LOGC;
    if (e >= E) return;
    int c = t & (C - 1);
    int s = __ldg(src + e);
    int d = __ldg(dst + e);
    float4 v = __ldg((const float4*)(g_work + MOFF) + s * C + c);
    red_add_v4(g_zero + AOFF + (d * C + c) * 4, v);
}

// generic small dense layer over nodes: out = f(scale_in * in) @ W (+ b) (* scale_out)
// thread computes 16 outputs for one node; JC = DOUT/16 threads per node.
template <int DIN, int DOUT, bool RELU, bool BIAS, bool SCALE_IN, bool SCALE_OUT,
          bool IN_ZEROBUF, int INOFF, int OUTOFF>
__global__ void k_mm(const float* __restrict__ W, const float* __restrict__ b) {
    constexpr int JC = DOUT / 16;
    __shared__ float sW[DIN * DOUT];
    __shared__ float sb[DOUT];
    for (int i = threadIdx.x; i < DIN * DOUT; i += blockDim.x) sW[i] = W[i];
    if (BIAS) {
        for (int i = threadIdx.x; i < DOUT; i += blockDim.x) sb[i] = b[i];
    }
    __syncthreads();

    int t = blockIdx.x * blockDim.x + threadIdx.x;
    int n = t / JC;
    int jc = t % JC;
    if (n >= NN) return;

    const float* in = (IN_ZEROBUF ? g_zero : g_work) + INOFF + n * DIN;
    float si = SCALE_IN ? g_work[OFF_NDST + n] : 1.0f;

    float acc[16];
#pragma unroll
    for (int j = 0; j < 16; j++) acc[j] = 0.0f;

#pragma unroll
    for (int k = 0; k < DIN; k += 4) {
        float4 v = __ldg((const float4*)(in + k));
        float vv[4] = {v.x * si, v.y * si, v.z * si, v.w * si};
#pragma unroll
        for (int kk = 0; kk < 4; kk++) {
#pragma unroll
            for (int j = 0; j < 16; j++) {
                acc[j] += vv[kk] * sW[(k + kk) * DOUT + jc * 16 + j];
            }
        }
    }

    float so = SCALE_OUT ? g_work[OFF_NSRC + n] : 1.0f;
    float4* o = (float4*)(g_work + OUTOFF + n * DOUT + jc * 16);
#pragma unroll
    for (int j4 = 0; j4 < 4; j4++) {
        float r[4];
#pragma unroll
        for (int k = 0; k < 4; k++) {
            float x = acc[j4 * 4 + k];
            if (BIAS) x += sb[jc * 16 + j4 * 4 + k];
            if (RELU) x = fmaxf(x, 0.0f);
            r[k] = x * so;
        }
        o[j4] = make_float4(r[0], r[1], r[2], r[3]);
    }
}

// fused: embed = agg2*norm_dst + b2 -> d_out; p3 = (relu(embed) @ W3) * norm_src
__global__ void k_embed_p3(const float* __restrict__ W3, const float* __restrict__ b2,
                           float* __restrict__ out_embed) {
    __shared__ float sW[32 * 16];
    __shared__ float sb[32];
    for (int i = threadIdx.x; i < 512; i += blockDim.x) sW[i] = W3[i];
    if (threadIdx.x < 32) sb[threadIdx.x] = b2[threadIdx.x];
    __syncthreads();

    int n = blockIdx.x * blockDim.x + threadIdx.x;
    if (n >= NN) return;

    float nd = g_work[OFF_NDST + n];
    float ns = g_work[OFF_NSRC + n];

    float tr[32];
    const float4* row = (const float4*)(g_zero + OFF_AGG2) + n * 8;
    float4* eo = (float4*)out_embed + n * 8;
#pragma unroll
    for (int c = 0; c < 8; c++) {
        float4 v = __ldg(row + c);
        v.x = v.x * nd + sb[c * 4 + 0];
        v.y = v.y * nd + sb[c * 4 + 1];
        v.z = v.z * nd + sb[c * 4 + 2];
        v.w = v.w * nd + sb[c * 4 + 3];
        eo[c] = v;
        tr[c * 4 + 0] = fmaxf(v.x, 0.0f);
        tr[c * 4 + 1] = fmaxf(v.y, 0.0f);
        tr[c * 4 + 2] = fmaxf(v.z, 0.0f);
        tr[c * 4 + 3] = fmaxf(v.w, 0.0f);
    }

    float acc[16];
#pragma unroll
    for (int j = 0; j < 16; j++) acc[j] = 0.0f;
#pragma unroll
    for (int k = 0; k < 32; k++) {
#pragma unroll
        for (int j = 0; j < 16; j++) acc[j] += tr[k] * sW[k * 16 + j];
    }

    float4* po = (float4*)(g_work + OFF_P3) + n * 4;
#pragma unroll
    for (int c = 0; c < 4; c++) {
        po[c] = make_float4(acc[c * 4 + 0] * ns, acc[c * 4 + 1] * ns,
                            acc[c * 4 + 2] * ns, acc[c * 4 + 3] * ns);
    }
}

// h_out = agg3 * norm_dst + b3   (16 floats/node = 4 float4)
__global__ void k_out3(const float* __restrict__ b3, float* __restrict__ out_h) {
    int t = blockIdx.x * blockDim.x + threadIdx.x;
    if (t >= NN * 4) return;
    int n = t >> 2;
    int c = t & 3;
    float nd = g_work[OFF_NDST + n];
    float4 v = __ldg((const float4*)(g_zero + OFF_AGG3) + t);
    float4 bb = __ldg((const float4*)b3 + c);
    v.x = v.x * nd + bb.x;
    v.y = v.y * nd + bb.y;
    v.z = v.z * nd + bb.z;
    v.w = v.w * nd + bb.w;
    ((float4*)out_h)[t] = v;
}

// ---------------- launch ----------------

extern "C" void kernel_launch(void* const* d_in, const int* in_sizes, int n_in,
                              void* d_out, int out_size) {
    const float* x  = (const float*)d_in[0];
    const float* W1 = (const float*)d_in[1];
    const float* b1 = (const float*)d_in[2];
    const float* W2 = (const float*)d_in[3];
    const float* b2 = (const float*)d_in[4];
    const float* W3 = (const float*)d_in[5];
    const float* b3 = (const float*)d_in[6];
    const int* src  = (const int*)d_in[7];
    const int* dst  = (const int*)d_in[8];
    float* out = (float*)d_out;
    int E = in_sizes[7];
    (void)n_in; (void)out_size;

    const int TB = 256;
    auto blk = [](long n, int tb) { return (int)((n + tb - 1) / tb); };

    // zero degrees + accumulators
    k_zero<<<blk(ZERO_FLOATS / 4, TB), TB>>>();
    // degrees + norms
    k_deg<<<blk(E, TB), TB>>>(src, dst, E);
    k_norm<<<blk(NN, TB), TB>>>();
    // layer 1: y1 = x * norm_src ; agg1 += y1[src] ; h1 = relu((agg1*norm_dst)@W1 + b1)
    k_scale_x<<<blk((long)NN * 16, TB), TB>>>(x);
    k_scatter<16, 4, OFF_Y1, OFF_AGG1><<<blk((long)E * 16, TB), TB>>>(src, dst, E);
    k_mm<64, 64, true, true, true, false, true, OFF_AGG1, OFF_H1>
        <<<blk((long)NN * 4, TB), TB>>>(W1, b1);
    // layer 2 (project-then-aggregate): p2 = (h1@W2)*norm_src ; agg2 += p2[src]
    k_mm<64, 32, false, false, false, true, false, OFF_H1, OFF_P2>
        <<<blk((long)NN * 2, TB), TB>>>(W2, nullptr);
    k_scatter<8, 3, OFF_P2, OFF_AGG2><<<blk((long)E * 8, TB), TB>>>(src, dst, E);
    // embed -> d_out[0 : 32*NN]; p3 = (relu(embed)@W3)*norm_src
    k_embed_p3<<<blk(NN, TB), TB>>>(W3, b2, out);
    // layer 3: agg3 += p3[src]; h = agg3*norm_dst + b3 -> d_out[32*NN : 48*NN]
    k_scatter<4, 2, OFF_P3, OFF_AGG3><<<blk((long)E * 4, TB), TB>>>(src, dst, E);
    k_out3<<<blk((long)NN * 4, TB), TB>>>(b3, out + 32 * NN);
}

// round 2
// speedup vs baseline: 1.2157x; 1.2157x over previous
#include <cuda_runtime.h>

#define NN 50000
#define NEMAX 1000000
#define NB 196          // ceil(NN/256)

// ---------------- scratch ----------------
// floats: [nsrc NN | ndst NN | agg1 64NN | h1 64NN | p2 32NN | agg2 32NN | p3 16NN | agg3 16NN]
__device__ __align__(256) float g_work[226 * NN];
// ints:   [ideg NN | odeg NN | rowptr NN+1 | cursor NN | part 256 | partpre 256 | csr NEMAX]
__device__ __align__(256) int g_int[4 * NN + 1 + 512 + NEMAX];

#define OFF_NSRC 0
#define OFF_NDST (NN)
#define OFF_AGG1 (2 * NN)
#define OFF_H1   (66 * NN)
#define OFF_P2   (130 * NN)
#define OFF_AGG2 (162 * NN)
#define OFF_P3   (194 * NN)
#define OFF_AGG3 (210 * NN)

#define IOFF_IDEG 0
#define IOFF_ODEG (NN)
#define IOFF_ROWP (2 * NN)
#define IOFF_CUR  (3 * NN + 1)
#define IOFF_PART (4 * NN + 1)
#define IOFF_PPRE (4 * NN + 1 + 256)
#define IOFF_CSR  (4 * NN + 1 + 512)

// ---------------- degree / norm ----------------

__global__ void k_zero_deg() {
    int i = blockIdx.x * blockDim.x + threadIdx.x;
    if (i < 2 * NN) g_int[i] = 0;
}

__global__ void k_deg(const int* __restrict__ src, const int* __restrict__ dst, int E) {
    int e = blockIdx.x * blockDim.x + threadIdx.x;
    if (e < E) {
        atomicAdd(&g_int[IOFF_ODEG + src[e]], 1);
        atomicAdd(&g_int[IOFF_IDEG + dst[e]], 1);
    }
}

__global__ void k_norm() {
    int i = blockIdx.x * blockDim.x + threadIdx.x;
    if (i < NN) {
        g_work[OFF_NSRC + i] = rsqrtf(fmaxf((float)g_int[IOFF_ODEG + i], 1.0f));
        g_work[OFF_NDST + i] = rsqrtf(fmaxf((float)g_int[IOFF_IDEG + i], 1.0f));
    }
}

// ---------------- CSR build (scan of in_deg) ----------------

__global__ void k_scan1() {
    __shared__ int sh[256];
    int i = blockIdx.x * 256 + threadIdx.x;
    sh[threadIdx.x] = (i < NN) ? g_int[IOFF_IDEG + i] : 0;
    __syncthreads();
    for (int o = 128; o > 0; o >>= 1) {
        if (threadIdx.x < o) sh[threadIdx.x] += sh[threadIdx.x + o];
        __syncthreads();
    }
    if (threadIdx.x == 0) g_int[IOFF_PART + blockIdx.x] = sh[0];
}

__global__ void k_scan2() {
    __shared__ int sh[256];
    int t = threadIdx.x;
    sh[t] = (t < NB) ? g_int[IOFF_PART + t] : 0;
    __syncthreads();
    if (t == 0) {
        int run = 0;
        for (int b = 0; b < NB; b++) { int v = sh[b]; sh[b] = run; run += v; }
    }
    __syncthreads();
    if (t < NB) g_int[IOFF_PPRE + t] = sh[t];
}

__global__ void k_scan3() {
    __shared__ int sh[256];
    int t = threadIdx.x;
    int i = blockIdx.x * 256 + t;
    int v = (i < NN) ? g_int[IOFF_IDEG + i] : 0;
    sh[t] = v;
    __syncthreads();
    for (int o = 1; o < 256; o <<= 1) {
        int x = (t >= o) ? sh[t - o] : 0;
        __syncthreads();
        sh[t] += x;
        __syncthreads();
    }
    int excl = sh[t] - v + g_int[IOFF_PPRE + blockIdx.x];
    if (i < NN) {
        g_int[IOFF_ROWP + i] = excl;
        g_int[IOFF_CUR + i] = excl;
    }
    if (i == NN - 1) g_int[IOFF_ROWP + NN] = excl + v;
}

__global__ void k_fill(const int* __restrict__ src, const int* __restrict__ dst, int E) {
    int e = blockIdx.x * blockDim.x + threadIdx.x;
    if (e < E) {
        int pos = atomicAdd(&g_int[IOFF_CUR + dst[e]], 1);
        g_int[IOFF_CSR + pos] = src[e];
    }
}

// ---------------- gather aggregation (no float atomics) ----------------
// C threads per dst node, thread c owns float4 chunk c of the row.
template <int C, int LOGC, bool L1, int MOFF, int AOFF>
__global__ void k_gather(const float* __restrict__ x) {
    int t = blockIdx.x * blockDim.x + threadIdx.x;
    int n = t >> LOGC;
    if (n >= NN) return;
    int c = t & (C - 1);
    int beg = __ldg(&g_int[IOFF_ROWP + n]);
    int end = __ldg(&g_int[IOFF_ROWP + n + 1]);
    const float4* msg = L1 ? (const float4*)x : (const float4*)(g_work + MOFF);

    float4 acc = make_float4(0.f, 0.f, 0.f, 0.f);
    int i = beg;
    for (; i + 1 < end; i += 2) {
        int s0 = __ldg(&g_int[IOFF_CSR + i]);
        int s1 = __ldg(&g_int[IOFF_CSR + i + 1]);
        float4 v0 = __ldg(msg + s0 * C + c);
        float4 v1 = __ldg(msg + s1 * C + c);
        float w0 = 1.0f, w1 = 1.0f;
        if (L1) { w0 = __ldg(&g_work[OFF_NSRC + s0]); w1 = __ldg(&g_work[OFF_NSRC + s1]); }
        acc.x += v0.x * w0 + v1.x * w1;
        acc.y += v0.y * w0 + v1.y * w1;
        acc.z += v0.z * w0 + v1.z * w1;
        acc.w += v0.w * w0 + v1.w * w1;
    }
    if (i < end) {
        int s0 = __ldg(&g_int[IOFF_CSR + i]);
        float4 v0 = __ldg(msg + s0 * C + c);
        float w0 = L1 ? __ldg(&g_work[OFF_NSRC + s0]) : 1.0f;
        acc.x += v0.x * w0; acc.y += v0.y * w0; acc.z += v0.z * w0; acc.w += v0.w * w0;
    }
    ((float4*)(g_work + AOFF))[n * C + c] = acc;
}

// ---------------- dense layers ----------------
// out = f(scale_in * in) @ W (+b) (* scale_out); DOUT/16 threads per node.
template <int DIN, int DOUT, bool RELU, bool BIAS, bool SCALE_IN, bool SCALE_OUT,
          int INOFF, int OUTOFF>
__global__ void k_mm(const float* __restrict__ W, const float* __restrict__ b) {
    constexpr int JC = DOUT / 16;
    __shared__ float sW[DIN * DOUT];
    __shared__ float sb[DOUT];
    for (int i = threadIdx.x; i < DIN * DOUT; i += blockDim.x) sW[i] = W[i];
    if (BIAS) for (int i = threadIdx.x; i < DOUT; i += blockDim.x) sb[i] = b[i];
    __syncthreads();

    int t = blockIdx.x * blockDim.x + threadIdx.x;
    int n = t / JC;
    int jc = t % JC;
    if (n >= NN) return;

    const float* in = g_work + INOFF + n * DIN;
    float si = SCALE_IN ? g_work[OFF_NDST + n] : 1.0f;

    float acc[16];
#pragma unroll
    for (int j = 0; j < 16; j++) acc[j] = 0.0f;
#pragma unroll
    for (int k = 0; k < DIN; k += 4) {
        float4 v = __ldg((const float4*)(in + k));
        float vv[4] = {v.x * si, v.y * si, v.z * si, v.w * si};
#pragma unroll
        for (int kk = 0; kk < 4; kk++) {
#pragma unroll
            for (int j = 0; j < 16; j++)
                acc[j] += vv[kk] * sW[(k + kk) * DOUT + jc * 16 + j];
        }
    }
    float so = SCALE_OUT ? g_work[OFF_NSRC + n] : 1.0f;
    float4* o = (float4*)(g_work + OUTOFF + n * DOUT + jc * 16);
#pragma unroll
    for (int j4 = 0; j4 < 4; j4++) {
        float r[4];
#pragma unroll
        for (int k = 0; k < 4; k++) {
            float x = acc[j4 * 4 + k];
            if (BIAS) x += sb[jc * 16 + j4 * 4 + k];
            if (RELU) x = fmaxf(x, 0.0f);
            r[k] = x * so;
        }
        o[j4] = make_float4(r[0], r[1], r[2], r[3]);
    }
}

// fused: embed = agg2*norm_dst + b2 -> d_out; p3 = (relu(embed) @ W3) * norm_src
__global__ void k_embed_p3(const float* __restrict__ W3, const float* __restrict__ b2,
                           float* __restrict__ out_embed) {
    __shared__ float sW[32 * 16];
    __shared__ float sb[32];
    for (int i = threadIdx.x; i < 512; i += blockDim.x) sW[i] = W3[i];
    if (threadIdx.x < 32) sb[threadIdx.x] = b2[threadIdx.x];
    __syncthreads();

    int n = blockIdx.x * blockDim.x + threadIdx.x;
    if (n >= NN) return;

    float nd = g_work[OFF_NDST + n];
    float ns = g_work[OFF_NSRC + n];

    float tr[32];
    const float4* row = (const float4*)(g_work + OFF_AGG2) + n * 8;
    float4* eo = (float4*)out_embed + n * 8;
#pragma unroll
    for (int c = 0; c < 8; c++) {
        float4 v = __ldg(row + c);
        v.x = v.x * nd + sb[c * 4 + 0];
        v.y = v.y * nd + sb[c * 4 + 1];
        v.z = v.z * nd + sb[c * 4 + 2];
        v.w = v.w * nd + sb[c * 4 + 3];
        eo[c] = v;
        tr[c * 4 + 0] = fmaxf(v.x, 0.0f);
        tr[c * 4 + 1] = fmaxf(v.y, 0.0f);
        tr[c * 4 + 2] = fmaxf(v.z, 0.0f);
        tr[c * 4 + 3] = fmaxf(v.w, 0.0f);
    }

    float acc[16];
#pragma unroll
    for (int j = 0; j < 16; j++) acc[j] = 0.0f;
#pragma unroll
    for (int k = 0; k < 32; k++) {
#pragma unroll
        for (int j = 0; j < 16; j++) acc[j] += tr[k] * sW[k * 16 + j];
    }
    float4* po = (float4*)(g_work + OFF_P3) + n * 4;
#pragma unroll
    for (int c = 0; c < 4; c++) {
        po[c] = make_float4(acc[c * 4 + 0] * ns, acc[c * 4 + 1] * ns,
                            acc[c * 4 + 2] * ns, acc[c * 4 + 3] * ns);
    }
}

// h_out = agg3 * norm_dst + b3
__global__ void k_out3(const float* __restrict__ b3, float* __restrict__ out_h) {
    int t = blockIdx.x * blockDim.x + threadIdx.x;
    if (t >= NN * 4) return;
    int n = t >> 2;
    int c = t & 3;
    float nd = g_work[OFF_NDST + n];
    float4 v = __ldg((const float4*)(g_work + OFF_AGG3) + t);
    float4 bb = __ldg((const float4*)b3 + c);
    v.x = v.x * nd + bb.x;
    v.y = v.y * nd + bb.y;
    v.z = v.z * nd + bb.z;
    v.w = v.w * nd + bb.w;
    ((float4*)out_h)[t] = v;
}

// ---------------- launch ----------------

extern "C" void kernel_launch(void* const* d_in, const int* in_sizes, int n_in,
                              void* d_out, int out_size) {
    const float* x  = (const float*)d_in[0];
    const float* W1 = (const float*)d_in[1];
    const float* b1 = (const float*)d_in[2];
    const float* W2 = (const float*)d_in[3];
    const float* b2 = (const float*)d_in[4];
    const float* W3 = (const float*)d_in[5];
    const float* b3 = (const float*)d_in[6];
    const int* src  = (const int*)d_in[7];
    const int* dst  = (const int*)d_in[8];
    float* out = (float*)d_out;
    int E = in_sizes[7];
    (void)n_in; (void)out_size;

    const int TB = 256;
    auto blk = [](long n, int tb) { return (int)((n + tb - 1) / tb); };

    // degrees + norms + CSR
    k_zero_deg<<<blk(2 * NN, TB), TB>>>();
    k_deg<<<blk(E, TB), TB>>>(src, dst, E);
    k_norm<<<blk(NN, TB), TB>>>();
    k_scan1<<<NB, 256>>>();
    k_scan2<<<1, 256>>>();
    k_scan3<<<NB, 256>>>();
    k_fill<<<blk(E, TB), TB>>>(src, dst, E);

    // layer 1: agg1[n] = sum_{s in N(n)} x[s]*nsrc[s]; h1 = relu((agg1*ndst)@W1+b1)
    k_gather<16, 4, true, 0, OFF_AGG1><<<blk((long)NN * 16, TB), TB>>>(x);
    k_mm<64, 64, true, true, true, false, OFF_AGG1, OFF_H1>
        <<<blk((long)NN * 4, TB), TB>>>(W1, b1);

    // layer 2: p2 = (h1@W2)*nsrc ; agg2 = gather(p2)
    k_mm<64, 32, false, false, false, true, OFF_H1, OFF_P2>
        <<<blk((long)NN * 2, TB), TB>>>(W2, nullptr);
    k_gather<8, 3, false, OFF_P2, OFF_AGG2><<<blk((long)NN * 8, TB), TB>>>(nullptr);

    // embed -> out[0:32NN]; p3 = (relu(embed)@W3)*nsrc
    k_embed_p3<<<blk(NN, TB), TB>>>(W3, b2, out);

    // layer 3: agg3 = gather(p3); h = agg3*ndst + b3 -> out[32NN:48NN]
    k_gather<4, 2, false, OFF_P3, OFF_AGG3><<<blk((long)NN * 4, TB), TB>>>(nullptr);
    k_out3<<<blk((long)NN * 4, TB), TB>>>(b3, out + 32 * NN);
}